// round 16
// baseline (speedup 1.0000x reference)
#include <cuda_runtime.h>
#include <cuda_fp16.h>
#include <cstdint>

#define BATCH 8192
#define NNODE 30
#define FEAT  256
#define MROWS (BATCH * NNODE)   // 245760
#define NTILES2 (MROWS / 32)    // 7680
#define PGRID 148

// ---------------- scratch (device globals) ----------------
__device__ float  g_adj[(size_t)BATCH * NNODE * NNODE];  // 29.5 MB
__device__ __half g_y1[(size_t)MROWS * FEAT];
__device__ __half g_h1[(size_t)MROWS * FEAT];
__device__ __half g_u2[(size_t)MROWS * FEAT];
__device__ __half g_w1[FEAT * FEAT], g_w2[FEAT * FEAT];

// ==================== helpers ====================
__device__ __forceinline__ uint32_t smem_to_u32(const void* p) {
    uint32_t a;
    asm("{ .reg .u64 t; cvta.to.shared.u64 t, %1; cvt.u32.u64 %0, t; }" : "=r"(a) : "l"(p));
    return a;
}
__device__ __forceinline__ void cpasync16(uint32_t saddr, const void* g) {
    asm volatile("cp.async.cg.shared.global [%0], [%1], 16;" :: "r"(saddr), "l"(g));
}
__device__ __forceinline__ void ldsm4(uint32_t* r, uint32_t addr) {
    asm volatile("ldmatrix.sync.aligned.m8n8.x4.shared.b16 {%0,%1,%2,%3}, [%4];"
        : "=r"(r[0]), "=r"(r[1]), "=r"(r[2]), "=r"(r[3]) : "r"(addr));
}
__device__ __forceinline__ void mma_f16(float* d, const uint32_t* a, uint32_t b0, uint32_t b1) {
    asm volatile(
        "mma.sync.aligned.m16n8k16.row.col.f32.f16.f16.f32 "
        "{%0,%1,%2,%3}, {%4,%5,%6,%7}, {%8,%9}, {%0,%1,%2,%3};"
        : "+f"(d[0]), "+f"(d[1]), "+f"(d[2]), "+f"(d[3])
        : "r"(a[0]), "r"(a[1]), "r"(a[2]), "r"(a[3]), "r"(b0), "r"(b1));
}
__device__ __forceinline__ unsigned long long pk2(float x, float y) {
    unsigned long long r;
    asm("mov.b64 %0, {%1, %2};" : "=l"(r) : "f"(x), "f"(y));
    return r;
}
__device__ __forceinline__ void upk2(unsigned long long v, float& x, float& y) {
    asm("mov.b64 {%0, %1}, %2;" : "=f"(x), "=f"(y) : "l"(v));
}
__device__ __forceinline__ unsigned long long fma2(unsigned long long a,
                                                   unsigned long long b,
                                                   unsigned long long c) {
    unsigned long long d;
    asm("fma.rn.f32x2 %0, %1, %2, %3;" : "=l"(d) : "l"(a), "l"(b), "l"(c));
    return d;
}

// =====================================================================
// prep_w: transpose W1/W2 to [N,K] K-major fp16
// =====================================================================
__global__ void prep_w(const float* __restrict__ W1, const float* __restrict__ W2,
                       __half* __restrict__ w1, __half* __restrict__ w2) {
    const int n = blockIdx.x, k = threadIdx.x;
    w1[n * 256 + k] = __float2half_rn(W1[k * 256 + n]);
    w2[n * 256 + k] = __float2half_rn(W2[k * 256 + n]);
}

// =====================================================================
// k_prep: adj = mean(graph, bands); y1 = adj @ x -> fp16  (R14 proven)
// =====================================================================
__global__ __launch_bounds__(128)
void k_prep(const float* __restrict__ graph, const float* __restrict__ x,
            float* __restrict__ adj_out, __half* __restrict__ y1) {
    __shared__ __align__(16) float adj_s[960];
    const int tid = threadIdx.x;
    const size_t b = blockIdx.x;

    const float* gp = graph + b * 4500;
    float* ao = adj_out + b * 900;
    for (int e = tid; e < 900; e += 128) {
        int i = e / 30, k = e - i * 30;
        float s = 0.2f * (gp[e] + gp[e + 900] + gp[e + 1800] + gp[e + 2700] + gp[e + 3600]);
        adj_s[i * 32 + k] = s;
        ao[e] = s;
    }
    if (tid < 60) adj_s[(tid >> 1) * 32 + 30 + (tid & 1)] = 0.f;

    const int j = tid * 2;
    const float* xp = x + b * 7680 + j;
    unsigned long long xr[32];
    #pragma unroll
    for (int k = 0; k < 30; ++k) {
        float2 v = *(const float2*)(xp + (size_t)k * 256);
        xr[k] = pk2(v.x, v.y);
    }
    xr[30] = 0ULL; xr[31] = 0ULL;
    __syncthreads();

    #pragma unroll 1
    for (int i = 0; i < 30; ++i) {
        unsigned long long acc = 0ULL;
        const float* ar = adj_s + i * 32;
        #pragma unroll
        for (int k4 = 0; k4 < 8; ++k4) {
            float4 a4 = *(const float4*)(ar + k4 * 4);
            acc = fma2(pk2(a4.x, a4.x), xr[k4 * 4 + 0], acc);
            acc = fma2(pk2(a4.y, a4.y), xr[k4 * 4 + 1], acc);
            acc = fma2(pk2(a4.z, a4.z), xr[k4 * 4 + 2], acc);
            acc = fma2(pk2(a4.w, a4.w), xr[k4 * 4 + 3], acc);
        }
        float y0, yy;
        upk2(acc, y0, yy);
        *(__half2*)(y1 + (b * 30 + i) * 256 + j) = __floats2half2_rn(y0, yy);
    }
}

// =====================================================================
// Persistent GEMM v2: K-split, B fragments in registers.
// grid=148, 512 thr / 16 warps = 8 warp_n (32 cols) x 2 warp_k (K=128).
// Tile = 32 rows. W loaded to smem once, each warp hoists its 8 kc of B
// fragments into 64 regs; tile loop = 2 A-ldsm + 8 HMMA per kc.
// warp_k partials combined via smem reduction; warp_k=0 does epilogue.
// smem: W [0,131072) 16 chunks 8KB; A [131072,+2x16384);
//       RED [163840,+32768); bias [196608,+1024)  -> 197632 total
// =====================================================================
#define P2_W    0u
#define P2_A    131072u
#define P2_RED  163840u
#define P2_BIAS 196608u
#define P2_TOTAL 197632

template <int MODE>
__global__ __launch_bounds__(512, 1)
void gemm_persist2(const __half* __restrict__ A, const __half* __restrict__ W,
                   const float* __restrict__ bias, __half* __restrict__ Out) {
    extern __shared__ char smem[];
    const uint32_t sb = smem_to_u32(smem);
    const int tid = threadIdx.x, lane = tid & 31, wid = tid >> 5;
    const int warp_n = wid & 7;        // 8 x 32-col slices
    const int warp_k = wid >> 3;       // 0: k[0,128), 1: k[128,256)
    const int k0 = warp_k * 8;         // first kc chunk

    // ---- W load to smem: 16 chunks x 8KB ----
    #pragma unroll
    for (int u = tid; u < 8192; u += 512) {
        int kc = u >> 9, v = u & 511;
        int n = v >> 1, half = v & 1;
        int row = n & 63, sub = n >> 6;
        uint32_t off = (uint32_t)kc * 8192u + (uint32_t)(row * 128)
                     + (((uint32_t)(sub * 32 + half * 16)) ^ ((uint32_t)(row & 7) << 4));
        cpasync16(sb + P2_W + off, W + (size_t)n * 256 + (size_t)kc * 16 + half * 8);
    }
    asm volatile("cp.async.commit_group;" ::: "memory");
    if (MODE == 1 && tid < 256) ((float*)(smem + P2_BIAS))[tid] = bias[tid];
    asm volatile("cp.async.wait_group 0;" ::: "memory");
    __syncthreads();

    // ---- hoist B fragments into registers (once) ----
    const int matv = lane >> 3;
    const int nB0 = warp_n * 32 + matv * 8 + (lane & 7);
    const uint32_t roB = (uint32_t)((nB0 & 63) * 128);
    const uint32_t baseB = (uint32_t)((nB0 >> 6) * 32);
    const uint32_t xorv = (uint32_t)((lane & 7) << 4);

    uint32_t bfr[8][2][4];
    #pragma unroll
    for (int kcl = 0; kcl < 8; ++kcl) {
        const uint32_t wst = sb + P2_W + (uint32_t)(k0 + kcl) * 8192u;
        ldsm4(bfr[kcl][0], wst + roB + (baseB ^ xorv));
        ldsm4(bfr[kcl][1], wst + roB + ((baseB + 16u) ^ xorv));
    }

    // ---- A tile loader: 16KB = 4 chunks [32 x 128B] SW128 ----
    auto aload = [&](int tile, int stage) {
        const __half* gA = A + (size_t)tile * 32 * 256;
        uint32_t st = sb + P2_A + (uint32_t)stage * 16384u;
        #pragma unroll
        for (int u = tid; u < 1024; u += 512) {
            int row = u >> 5, s = u & 31;
            int c = s >> 3, ss = s & 7;
            uint32_t off = (uint32_t)c * 4096u + (uint32_t)(row * 128)
                         + (((uint32_t)ss * 16u) ^ ((uint32_t)(row & 7) << 4));
            cpasync16(st + off, gA + (size_t)row * 256 + s * 8);
        }
        asm volatile("cp.async.commit_group;" ::: "memory");
    };

    // ---- A ldsm addressing ----
    const int rA0 = (matv & 1) * 8 + (lane & 7);     // row within 32 (+ mt*16)
    const int kAoff = (matv >> 1) * 16;
    const int g = lane >> 2, cq = (lane & 3) * 2;

    int tile = blockIdx.x;
    aload(tile, 0);
    int it = 0;

    #pragma unroll 1
    for (; tile < NTILES2; tile += PGRID, ++it) {
        const int stage = it & 1;
        asm volatile("cp.async.wait_group 0;" ::: "memory");
        __syncthreads();
        if (tile + PGRID < NTILES2) aload(tile + PGRID, stage ^ 1);

        const uint32_t ab = sb + P2_A + (uint32_t)stage * 16384u;
        float acc[2][4][4];
        #pragma unroll
        for (int m = 0; m < 2; ++m)
            #pragma unroll
            for (int j = 0; j < 4; ++j)
                #pragma unroll
                for (int q = 0; q < 4; ++q) acc[m][j][q] = 0.f;

        #pragma unroll
        for (int kcl = 0; kcl < 8; ++kcl) {
            const int kc = k0 + kcl;
            const uint32_t abase = ab + (uint32_t)(kc >> 2) * 4096u;
            const uint32_t aco = ((uint32_t)((kc & 3) * 32 + kAoff)) ^ xorv;
            uint32_t a_f[2][4];
            ldsm4(a_f[0], abase + (uint32_t)(rA0 * 128) + aco);
            ldsm4(a_f[1], abase + (uint32_t)((rA0 + 16) * 128) + aco);
            #pragma unroll
            for (int mt = 0; mt < 2; ++mt)
                #pragma unroll
                for (int jj = 0; jj < 4; ++jj)
                    mma_f16(acc[mt][jj], a_f[mt], bfr[kcl][0][jj], bfr[kcl][1][jj]);
        }

        // ---- K-split reduction: warp_k=1 stores, warp_k=0 adds ----
        float* red = (float*)(smem + P2_RED) + (warp_n * 32 + lane) * 32;
        if (warp_k == 1) {
            #pragma unroll
            for (int mt = 0; mt < 2; ++mt)
                #pragma unroll
                for (int jj = 0; jj < 4; ++jj)
                    *(float4*)(red + (mt * 4 + jj) * 4) = *(float4*)acc[mt][jj];
        }
        __syncthreads();
        if (warp_k == 0) {
            #pragma unroll
            for (int mt = 0; mt < 2; ++mt)
                #pragma unroll
                for (int jj = 0; jj < 4; ++jj) {
                    float4 p = *(const float4*)(red + (mt * 4 + jj) * 4);
                    acc[mt][jj][0] += p.x;
                    acc[mt][jj][1] += p.y;
                    acc[mt][jj][2] += p.z;
                    acc[mt][jj][3] += p.w;
                }
            // ---- epilogue ----
            #pragma unroll
            for (int mt = 0; mt < 2; ++mt) {
                const size_t r0 = (size_t)tile * 32 + mt * 16 + g;
                #pragma unroll
                for (int j = 0; j < 4; ++j) {
                    const int col = warp_n * 32 + j * 8 + cq;
                    if (MODE == 1) {
                        const float* bs = (const float*)(smem + P2_BIAS);
                        float bb0 = bs[col], bb1 = bs[col + 1];
                        *(__half2*)(Out + r0 * 256 + col) = __floats2half2_rn(
                            fmaxf(acc[mt][j][0] + bb0, 0.f), fmaxf(acc[mt][j][1] + bb1, 0.f));
                        *(__half2*)(Out + (r0 + 8) * 256 + col) = __floats2half2_rn(
                            fmaxf(acc[mt][j][2] + bb0, 0.f), fmaxf(acc[mt][j][3] + bb1, 0.f));
                    } else {
                        *(__half2*)(Out + r0 * 256 + col) =
                            __floats2half2_rn(acc[mt][j][0], acc[mt][j][1]);
                        *(__half2*)(Out + (r0 + 8) * 256 + col) =
                            __floats2half2_rn(acc[mt][j][2], acc[mt][j][3]);
                    }
                }
            }
        }
    }
}

// =====================================================================
// k_final: g2 = adj @ u2; fused tail (R14 proven)
// =====================================================================
__global__ __launch_bounds__(512)
void k_final(const float* __restrict__ adj, const __half* __restrict__ u2,
             const float* __restrict__ b2g, const float* __restrict__ wling,
             const float* __restrict__ bling, const float* __restrict__ Wheadg,
             const float* __restrict__ bheadg, float* __restrict__ out) {
    __shared__ __align__(16) float adj_s[4 * 960];
    __shared__ float red[4][30][4];
    const int tid = threadIdx.x;
    const int b = tid >> 7, t2 = tid & 127, w = t2 >> 5;
    const size_t b0 = (size_t)blockIdx.x * 4;

    for (int e = tid; e < 3600; e += 512) {
        int bb = e / 900, i = e - bb * 900;
        adj_s[bb * 960 + (i / 30) * 32 + (i % 30)] = adj[(b0 + bb) * 900 + i];
    }
    if (tid < 240) {
        int bb = tid / 60, r = (tid % 60) >> 1;
        adj_s[bb * 960 + r * 32 + 30 + (tid & 1)] = 0.f;
    }

    const int j = t2 * 2;
    const __half* up = u2 + (b0 + b) * 7680 + j;
    unsigned long long uk[32];
    #pragma unroll
    for (int k = 0; k < 30; ++k) {
        float2 v = __half22float2(*(const __half2*)(up + (size_t)k * 256));
        uk[k] = pk2(v.x, v.y);
    }
    uk[30] = 0ULL; uk[31] = 0ULL;
    const float b2v0 = __ldg(b2g + j), b2v1 = __ldg(b2g + j + 1);
    const float wl0 = __ldg(wling + j), wl1 = __ldg(wling + j + 1);
    __syncthreads();

    const float* ar = adj_s + b * 960;
    #pragma unroll 1
    for (int i = 0; i < 30; ++i) {
        unsigned long long acc = 0ULL;
        const float* arow = ar + i * 32;
        #pragma unroll
        for (int k4 = 0; k4 < 8; ++k4) {
            float4 a4 = *(const float4*)(arow + k4 * 4);
            acc = fma2(pk2(a4.x, a4.x), uk[k4 * 4 + 0], acc);
            acc = fma2(pk2(a4.y, a4.y), uk[k4 * 4 + 1], acc);
            acc = fma2(pk2(a4.z, a4.z), uk[k4 * 4 + 2], acc);
            acc = fma2(pk2(a4.w, a4.w), uk[k4 * 4 + 3], acc);
        }
        float s0, s1;
        upk2(acc, s0, s1);
        float p = fmaxf(s0 + b2v0, 0.f) * wl0 + fmaxf(s1 + b2v1, 0.f) * wl1;
        #pragma unroll
        for (int o = 16; o > 0; o >>= 1) p += __shfl_xor_sync(0xffffffffu, p, o);
        if ((t2 & 31) == 0) red[b][i][w] = p;
    }
    __syncthreads();

    if (tid < 36) {
        const int bb = tid / 9, c = tid - bb * 9;
        const float bl = __ldg(bling);
        float s = __ldg(bheadg + c);
        #pragma unroll
        for (int i = 0; i < 30; ++i) {
            float xl = fmaxf(red[bb][i][0] + red[bb][i][1] + red[bb][i][2] + red[bb][i][3] + bl, 0.f);
            s = fmaf(xl, __ldg(Wheadg + c * 30 + i), s);
        }
        out[(b0 + bb) * 9 + c] = s;
    }
}

// =====================================================================
extern "C" void kernel_launch(void* const* d_in, const int* in_sizes, int n_in,
                              void* d_out, int out_size) {
    const float* real  = (const float*)d_in[0];
    const float* graph = (const float*)d_in[2];
    const float* W1    = (const float*)d_in[3];
    const float* b1    = (const float*)d_in[4];
    const float* W2    = (const float*)d_in[5];
    const float* b2    = (const float*)d_in[6];
    const float* wlin  = (const float*)d_in[7];
    const float* blin  = (const float*)d_in[8];
    const float* Whead = (const float*)d_in[9];
    const float* bhead = (const float*)d_in[10];
    float* out = (float*)d_out;

    float *adj_p;
    __half *y1_p, *h1_p, *u2_p, *w1_p, *w2_p;
    cudaGetSymbolAddress((void**)&adj_p, g_adj);
    cudaGetSymbolAddress((void**)&y1_p,  g_y1);
    cudaGetSymbolAddress((void**)&h1_p,  g_h1);
    cudaGetSymbolAddress((void**)&u2_p,  g_u2);
    cudaGetSymbolAddress((void**)&w1_p,  g_w1);
    cudaGetSymbolAddress((void**)&w2_p,  g_w2);

    cudaFuncSetAttribute(gemm_persist2<1>, cudaFuncAttributeMaxDynamicSharedMemorySize, P2_TOTAL);
    cudaFuncSetAttribute(gemm_persist2<2>, cudaFuncAttributeMaxDynamicSharedMemorySize, P2_TOTAL);

    // 1. weight transpose to fp16 [N,K]
    prep_w<<<256, 256>>>(W1, W2, w1_p, w2_p);
    // 2. adj = mean(graph); y1 = adj @ real (fp16)
    k_prep<<<BATCH, 128>>>(graph, real, adj_p, y1_p);
    // 3. h1 = relu(y1 @ W1 + b1)  (persistent, B-in-regs, K-split)
    gemm_persist2<1><<<PGRID, 512, P2_TOTAL>>>(y1_p, w1_p, b1, h1_p);
    // 4. u2 = h1 @ W2
    gemm_persist2<2><<<PGRID, 512, P2_TOTAL>>>(h1_p, w2_p, nullptr, u2_p);
    // 5. fused: g2 = adj@u2; relu(+b2).wlin; relu(+blin); head -> out
    k_final<<<BATCH / 4, 512>>>(adj_p, u2_p, b2, wlin, blin, Whead, bhead, out);
}

// round 17
// speedup vs baseline: 1.5208x; 1.5208x over previous
#include <cuda_runtime.h>
#include <cuda_fp16.h>
#include <cstdint>

#define BATCH 8192
#define NNODE 30
#define FEAT  256
#define MROWS (BATCH * NNODE)   // 245760
#define NTILES (MROWS / 64)     // 3840  (gemm1 tiles)
#define NTILESF (BATCH / 2)     // 4096  (fused gemm2 tiles: 2 batches)
#define PGRID 148

// ---------------- scratch (device globals) ----------------
__device__ float  g_adj[(size_t)BATCH * NNODE * NNODE];  // 29.5 MB
__device__ __half g_y1[(size_t)MROWS * FEAT];
__device__ __half g_h1[(size_t)MROWS * FEAT];
__device__ __half g_w1[FEAT * FEAT], g_w2[FEAT * FEAT];

// ==================== helpers ====================
__device__ __forceinline__ uint32_t smem_to_u32(const void* p) {
    uint32_t a;
    asm("{ .reg .u64 t; cvta.to.shared.u64 t, %1; cvt.u32.u64 %0, t; }" : "=r"(a) : "l"(p));
    return a;
}
__device__ __forceinline__ void cpasync16(uint32_t saddr, const void* g) {
    asm volatile("cp.async.cg.shared.global [%0], [%1], 16;" :: "r"(saddr), "l"(g));
}
__device__ __forceinline__ void ldsm4(uint32_t* r, uint32_t addr) {
    asm volatile("ldmatrix.sync.aligned.m8n8.x4.shared.b16 {%0,%1,%2,%3}, [%4];"
        : "=r"(r[0]), "=r"(r[1]), "=r"(r[2]), "=r"(r[3]) : "r"(addr));
}
__device__ __forceinline__ void mma_f16(float* d, const uint32_t* a, uint32_t b0, uint32_t b1) {
    asm volatile(
        "mma.sync.aligned.m16n8k16.row.col.f32.f16.f16.f32 "
        "{%0,%1,%2,%3}, {%4,%5,%6,%7}, {%8,%9}, {%0,%1,%2,%3};"
        : "+f"(d[0]), "+f"(d[1]), "+f"(d[2]), "+f"(d[3])
        : "r"(a[0]), "r"(a[1]), "r"(a[2]), "r"(a[3]), "r"(b0), "r"(b1));
}
__device__ __forceinline__ unsigned long long pk2(float x, float y) {
    unsigned long long r;
    asm("mov.b64 %0, {%1, %2};" : "=l"(r) : "f"(x), "f"(y));
    return r;
}
__device__ __forceinline__ void upk2(unsigned long long v, float& x, float& y) {
    asm("mov.b64 {%0, %1}, %2;" : "=f"(x), "=f"(y) : "l"(v));
}
__device__ __forceinline__ unsigned long long fma2(unsigned long long a,
                                                   unsigned long long b,
                                                   unsigned long long c) {
    unsigned long long d;
    asm("fma.rn.f32x2 %0, %1, %2, %3;" : "=l"(d) : "l"(a), "l"(b), "l"(c));
    return d;
}

// =====================================================================
// prep_w: transpose W1/W2 to [N,K] K-major fp16
// =====================================================================
__global__ void prep_w(const float* __restrict__ W1, const float* __restrict__ W2,
                       __half* __restrict__ w1, __half* __restrict__ w2) {
    const int n = blockIdx.x, k = threadIdx.x;
    w1[n * 256 + k] = __float2half_rn(W1[k * 256 + n]);
    w2[n * 256 + k] = __float2half_rn(W2[k * 256 + n]);
}

// =====================================================================
// k_prep: adj = mean(graph, bands); y1 = adj @ x -> fp16  (R14 proven)
// =====================================================================
__global__ __launch_bounds__(128)
void k_prep(const float* __restrict__ graph, const float* __restrict__ x,
            float* __restrict__ adj_out, __half* __restrict__ y1) {
    __shared__ __align__(16) float adj_s[960];
    const int tid = threadIdx.x;
    const size_t b = blockIdx.x;

    const float* gp = graph + b * 4500;
    float* ao = adj_out + b * 900;
    for (int e = tid; e < 900; e += 128) {
        int i = e / 30, k = e - i * 30;
        float s = 0.2f * (gp[e] + gp[e + 900] + gp[e + 1800] + gp[e + 2700] + gp[e + 3600]);
        adj_s[i * 32 + k] = s;
        ao[e] = s;
    }
    if (tid < 60) adj_s[(tid >> 1) * 32 + 30 + (tid & 1)] = 0.f;

    const int j = tid * 2;
    const float* xp = x + b * 7680 + j;
    unsigned long long xr[32];
    #pragma unroll
    for (int k = 0; k < 30; ++k) {
        float2 v = *(const float2*)(xp + (size_t)k * 256);
        xr[k] = pk2(v.x, v.y);
    }
    xr[30] = 0ULL; xr[31] = 0ULL;
    __syncthreads();

    #pragma unroll 1
    for (int i = 0; i < 30; ++i) {
        unsigned long long acc = 0ULL;
        const float* ar = adj_s + i * 32;
        #pragma unroll
        for (int k4 = 0; k4 < 8; ++k4) {
            float4 a4 = *(const float4*)(ar + k4 * 4);
            acc = fma2(pk2(a4.x, a4.x), xr[k4 * 4 + 0], acc);
            acc = fma2(pk2(a4.y, a4.y), xr[k4 * 4 + 1], acc);
            acc = fma2(pk2(a4.z, a4.z), xr[k4 * 4 + 2], acc);
            acc = fma2(pk2(a4.w, a4.w), xr[k4 * 4 + 3], acc);
        }
        float y0, yy;
        upk2(acc, y0, yy);
        *(__half2*)(y1 + (b * 30 + i) * 256 + j) = __floats2half2_rn(y0, yy);
    }
}

// =====================================================================
// Persistent GEMM (R10/R14 proven): W resident, 512 thr, warp tile 32x32.
// Out = relu(C+bias) -> fp16 (h1)
// =====================================================================
#define PSM_W    0u
#define PSM_A    131072u
#define PSM_BIAS 196608u
#define PSM_TOTAL 197632

__global__ __launch_bounds__(512, 1)
void gemm_persist(const __half* __restrict__ A, const __half* __restrict__ W,
                  const float* __restrict__ bias, __half* __restrict__ Out) {
    extern __shared__ char smem[];
    const uint32_t sb = smem_to_u32(smem);
    const int tid = threadIdx.x, lane = tid & 31, wid = tid >> 5;
    const int warp_m = wid & 1, warp_n = wid >> 1;

    #pragma unroll
    for (int u = tid; u < 8192; u += 512) {
        int kc = u >> 9, v = u & 511;
        int n = v >> 1, half = v & 1;
        int row = n & 63, sub = n >> 6;
        uint32_t off = (uint32_t)kc * 8192u + (uint32_t)(row * 128)
                     + (((uint32_t)(sub * 32 + half * 16)) ^ ((uint32_t)(row & 7) << 4));
        cpasync16(sb + PSM_W + off, W + (size_t)n * 256 + (size_t)kc * 16 + half * 8);
    }
    asm volatile("cp.async.commit_group;" ::: "memory");
    if (tid < 256) ((float*)(smem + PSM_BIAS))[tid] = bias[tid];

    auto aload = [&](int tile, int stage) {
        const __half* gA = A + (size_t)tile * 64 * 256;
        uint32_t st = sb + PSM_A + (uint32_t)stage * 32768u;
        #pragma unroll
        for (int u = tid; u < 2048; u += 512) {
            int row = u >> 5, s = u & 31;
            int c = s >> 3, ss = s & 7;
            uint32_t off = (uint32_t)c * 8192u + (uint32_t)(row * 128)
                         + (((uint32_t)ss * 16u) ^ ((uint32_t)(row & 7) << 4));
            cpasync16(st + off, gA + (size_t)row * 256 + s * 8);
        }
        asm volatile("cp.async.commit_group;" ::: "memory");
    };

    const int matv = lane >> 3;
    const int rA0 = warp_m * 32 + (matv & 1) * 8 + (lane & 7);
    const int kAoff = (matv >> 1) * 16;
    const int nB0 = warp_n * 32 + matv * 8 + (lane & 7);
    const uint32_t roB = (uint32_t)((nB0 & 63) * 128);
    const uint32_t baseB = (uint32_t)((nB0 >> 6) * 32);
    const uint32_t xorv = (uint32_t)((lane & 7) << 4);
    const int g = lane >> 2, cq = (lane & 3) * 2;

    int tile = blockIdx.x;
    aload(tile, 0);
    int it = 0;

    #pragma unroll 1
    for (; tile < NTILES; tile += PGRID, ++it) {
        const int stage = it & 1;
        asm volatile("cp.async.wait_group 0;" ::: "memory");
        __syncthreads();
        if (tile + PGRID < NTILES) aload(tile + PGRID, stage ^ 1);

        const uint32_t ab = sb + PSM_A + (uint32_t)stage * 32768u;
        float acc[2][4][4];
        #pragma unroll
        for (int m = 0; m < 2; ++m)
            #pragma unroll
            for (int j = 0; j < 4; ++j)
                #pragma unroll
                for (int q = 0; q < 4; ++q) acc[m][j][q] = 0.f;

        #pragma unroll 4
        for (int kc = 0; kc < 16; ++kc) {
            const uint32_t abase = ab + (uint32_t)(kc >> 2) * 8192u;
            const uint32_t aco = ((uint32_t)((kc & 3) * 32 + kAoff)) ^ xorv;
            uint32_t a_f[2][4];
            #pragma unroll
            for (int mt = 0; mt < 2; ++mt)
                ldsm4(a_f[mt], abase + (uint32_t)((rA0 + mt * 16) * 128) + aco);

            const uint32_t wst = sb + PSM_W + (uint32_t)kc * 8192u;
            uint32_t b0[4], b1[4];
            ldsm4(b0, wst + roB + (baseB ^ xorv));
            ldsm4(b1, wst + roB + ((baseB + 16u) ^ xorv));
            #pragma unroll
            for (int mt = 0; mt < 2; ++mt)
                #pragma unroll
                for (int jj = 0; jj < 4; ++jj)
                    mma_f16(acc[mt][jj], a_f[mt], b0[jj], b1[jj]);
        }

        #pragma unroll
        for (int mt = 0; mt < 2; ++mt) {
            const size_t r0 = (size_t)tile * 64 + warp_m * 32 + mt * 16 + g;
            #pragma unroll
            for (int j = 0; j < 4; ++j) {
                const int col = warp_n * 32 + j * 8 + cq;
                const float* bs = (const float*)(smem + PSM_BIAS);
                float bb0 = bs[col], bb1 = bs[col + 1];
                *(__half2*)(Out + r0 * 256 + col) = __floats2half2_rn(
                    fmaxf(acc[mt][j][0] + bb0, 0.f), fmaxf(acc[mt][j][1] + bb1, 0.f));
                *(__half2*)(Out + (r0 + 8) * 256 + col) = __floats2half2_rn(
                    fmaxf(acc[mt][j][2] + bb0, 0.f), fmaxf(acc[mt][j][3] + bb1, 0.f));
            }
        }
    }
}

// =====================================================================
// gemm_fused: u2 = h1 @ W2 on batch-aligned tiles (2 batches/tile,
// 60 real rows padded to 64), u2 kept in SMEM (overwrites consumed A
// stage), then fused: g2 = adj @ u2; relu(+b2).wlin; relu(+blin); head.
// Writes out[tile*2 + b, 9] directly. No u2 gmem traffic, no k_final.
// smem: W[0,131072) | A 2x32768 [131072,196608) | adj 7680 [196608)
//       b2+wlin 2048 [204288) | red 960 [206336) | xl 240 [207296)
// =====================================================================
#define GF_W    0u
#define GF_A    131072u
#define GF_ADJ  196608u
#define GF_CW   204288u
#define GF_RED  206336u
#define GF_XL   207296u
#define GF_TOTAL 207616

__global__ __launch_bounds__(512, 1)
void gemm_fused(const __half* __restrict__ A, const __half* __restrict__ W,
                const float* __restrict__ adjg,
                const float* __restrict__ b2g, const float* __restrict__ wling,
                const float* __restrict__ bling, const float* __restrict__ Wheadg,
                const float* __restrict__ bheadg, float* __restrict__ out) {
    extern __shared__ char smem[];
    const uint32_t sb = smem_to_u32(smem);
    const int tid = threadIdx.x, lane = tid & 31, wid = tid >> 5;
    const int warp_m = wid & 1, warp_n = wid >> 1;
    float* adj_s = (float*)(smem + GF_ADJ);
    float* red   = (float*)(smem + GF_RED);
    float* xls   = (float*)(smem + GF_XL);

    // ---- W resident load ----
    #pragma unroll
    for (int u = tid; u < 8192; u += 512) {
        int kc = u >> 9, v = u & 511;
        int n = v >> 1, half = v & 1;
        int row = n & 63, sub = n >> 6;
        uint32_t off = (uint32_t)kc * 8192u + (uint32_t)(row * 128)
                     + (((uint32_t)(sub * 32 + half * 16)) ^ ((uint32_t)(row & 7) << 4));
        cpasync16(sb + GF_W + off, W + (size_t)n * 256 + (size_t)kc * 16 + half * 8);
    }
    asm volatile("cp.async.commit_group;" ::: "memory");
    if (tid < 256) {
        ((float*)(smem + GF_CW))[tid] = b2g[tid];
        ((float*)(smem + GF_CW + 1024u))[tid] = wling[tid];
    }
    // zero adj k-pad entries once (k = 30,31 of each row)
    if (tid < 120) {
        int b = tid / 60, r = (tid % 60) >> 1;
        adj_s[b * 960 + r * 32 + 30 + (tid & 1)] = 0.f;
    }

    // ---- A tile loader: 60 real rows at smem rows 0..29, 32..61;
    //      pad rows 30,31,62,63 zeroed every load ----
    auto aload = [&](int tile, int stage) {
        const __half* gA = A + (size_t)tile * 60 * 256;
        uint32_t st = sb + GF_A + (uint32_t)stage * 32768u;
        #pragma unroll 1
        for (int u = tid; u < 1920; u += 512) {
            int row60 = u >> 5, s = u & 31;
            int c = s >> 3, ss = s & 7;
            int smr = row60 + (row60 >= 30 ? 2 : 0);
            uint32_t off = (uint32_t)c * 8192u + (uint32_t)(smr * 128)
                         + (((uint32_t)ss * 16u) ^ ((uint32_t)(smr & 7) << 4));
            cpasync16(st + off, gA + (size_t)row60 * 256 + s * 8);
        }
        if (tid < 128) {
            int zr = tid >> 5;                       // 0..3
            int row = 30 + (zr & 1) + (zr >> 1) * 32; // 30,31,62,63
            int c = (tid >> 3) & 3, ss = tid & 7;
            uint32_t off = (uint32_t)c * 8192u + (uint32_t)(row * 128)
                         + (((uint32_t)ss * 16u) ^ ((uint32_t)(row & 7) << 4));
            *(uint4*)(smem + GF_A + stage * 32768 + off) = make_uint4(0, 0, 0, 0);
        }
        asm volatile("cp.async.commit_group;" ::: "memory");
    };

    // ---- MMA addressing (R10) ----
    const int matv = lane >> 3;
    const int rA0 = warp_m * 32 + (matv & 1) * 8 + (lane & 7);
    const int kAoff = (matv >> 1) * 16;
    const int nB0 = warp_n * 32 + matv * 8 + (lane & 7);
    const uint32_t roB = (uint32_t)((nB0 & 63) * 128);
    const uint32_t baseB = (uint32_t)((nB0 >> 6) * 32);
    const uint32_t xorv = (uint32_t)((lane & 7) << 4);
    const int g = lane >> 2, cq = (lane & 3) * 2;

    // contraction thread mapping
    const int cb = (tid >> 7) & 1;     // batch within tile
    const int cih = tid >> 8;          // i half
    const int ct2 = tid & 127;         // column pair owner
    const int cw = ct2 >> 5;           // warp within (b,ihalf) group

    int tile = blockIdx.x;
    aload(tile, 0);
    int it = 0;

    #pragma unroll 1
    for (; tile < NTILESF; tile += PGRID, ++it) {
        const int stage = it & 1;

        // adj prefetch to regs (LDG latency hidden behind wait+MMA)
        float adjreg[4];
        const float* agp = adjg + (size_t)tile * 1800;
        #pragma unroll
        for (int q = 0; q < 4; ++q) {
            int e = tid + q * 512;
            adjreg[q] = (e < 1800) ? __ldg(agp + e) : 0.f;
        }

        asm volatile("cp.async.wait_group 0;" ::: "memory");
        __syncthreads();
        if (tile + PGRID < NTILESF) aload(tile + PGRID, stage ^ 1);

        const uint32_t ab = sb + GF_A + (uint32_t)stage * 32768u;
        float acc[2][4][4];
        #pragma unroll
        for (int m = 0; m < 2; ++m)
            #pragma unroll
            for (int j = 0; j < 4; ++j)
                #pragma unroll
                for (int q = 0; q < 4; ++q) acc[m][j][q] = 0.f;

        #pragma unroll 4
        for (int kc = 0; kc < 16; ++kc) {
            const uint32_t abase = ab + (uint32_t)(kc >> 2) * 8192u;
            const uint32_t aco = ((uint32_t)((kc & 3) * 32 + kAoff)) ^ xorv;
            uint32_t a_f[2][4];
            #pragma unroll
            for (int mt = 0; mt < 2; ++mt)
                ldsm4(a_f[mt], abase + (uint32_t)((rA0 + mt * 16) * 128) + aco);

            const uint32_t wst = sb + GF_W + (uint32_t)kc * 8192u;
            uint32_t b0[4], b1[4];
            ldsm4(b0, wst + roB + (baseB ^ xorv));
            ldsm4(b1, wst + roB + ((baseB + 16u) ^ xorv));
            #pragma unroll
            for (int mt = 0; mt < 2; ++mt)
                #pragma unroll
                for (int jj = 0; jj < 4; ++jj)
                    mma_f16(acc[mt][jj], a_f[mt], b0[jj], b1[jj]);
        }
        __syncthreads();   // all ldsm reads of this stage done

        // ---- store u2 (fp16, row-swizzled) into the consumed A stage;
        //      store adj regs into adj_s (padded rows) ----
        {
            char* stg = smem + GF_A + stage * 32768;
            #pragma unroll
            for (int mt = 0; mt < 2; ++mt) {
                #pragma unroll
                for (int half = 0; half < 2; ++half) {
                    int row = warp_m * 32 + mt * 16 + half * 8 + g;
                    uint32_t rbase = (uint32_t)(row * 512);
                    uint32_t sw = ((uint32_t)(row & 7)) << 4;
                    #pragma unroll
                    for (int j = 0; j < 4; ++j) {
                        int col = warp_n * 32 + j * 8 + cq;
                        uint32_t boff = rbase + (((uint32_t)(col * 2)) ^ sw);
                        *(__half2*)(stg + boff) = __floats2half2_rn(
                            acc[mt][j][half * 2], acc[mt][j][half * 2 + 1]);
                    }
                }
            }
            #pragma unroll
            for (int q = 0; q < 4; ++q) {
                int e = tid + q * 512;
                if (e < 1800) {
                    int b = e / 900, idx = e - b * 900;
                    adj_s[b * 960 + (idx / 30) * 32 + (idx % 30)] = adjreg[q];
                }
            }
        }
        __syncthreads();

        // ---- contraction: g2 = adj @ u2; p = relu(+b2).wlin ----
        {
            const char* ub = smem + GF_A + stage * 32768 + cb * 32 * 512;
            unsigned long long uk[32];
            #pragma unroll
            for (int k = 0; k < 30; ++k) {
                uint32_t boff = (uint32_t)(k * 512)
                              + (((uint32_t)(ct2 * 4)) ^ (((uint32_t)(k & 7)) << 4));
                float2 v = __half22float2(*(const __half2*)(ub + boff));
                uk[k] = pk2(v.x, v.y);
            }
            uk[30] = 0ULL; uk[31] = 0ULL;
            const float* cwb = (const float*)(smem + GF_CW);
            const float b2v0 = cwb[ct2 * 2], b2v1 = cwb[ct2 * 2 + 1];
            const float wl0 = cwb[256 + ct2 * 2], wl1 = cwb[256 + ct2 * 2 + 1];
            const float* ar = adj_s + cb * 960;
            const int i0 = cih * 15;
            #pragma unroll 1
            for (int i = i0; i < i0 + 15; ++i) {
                unsigned long long acc2 = 0ULL;
                const float* arow = ar + i * 32;
                #pragma unroll
                for (int k4 = 0; k4 < 8; ++k4) {
                    float4 a4 = *(const float4*)(arow + k4 * 4);
                    acc2 = fma2(pk2(a4.x, a4.x), uk[k4 * 4 + 0], acc2);
                    acc2 = fma2(pk2(a4.y, a4.y), uk[k4 * 4 + 1], acc2);
                    acc2 = fma2(pk2(a4.z, a4.z), uk[k4 * 4 + 2], acc2);
                    acc2 = fma2(pk2(a4.w, a4.w), uk[k4 * 4 + 3], acc2);
                }
                float s0, s1;
                upk2(acc2, s0, s1);
                float p = fmaxf(s0 + b2v0, 0.f) * wl0 + fmaxf(s1 + b2v1, 0.f) * wl1;
                #pragma unroll
                for (int o = 16; o > 0; o >>= 1) p += __shfl_xor_sync(0xffffffffu, p, o);
                if ((ct2 & 31) == 0) red[(cb * 30 + i) * 4 + cw] = p;
            }
        }
        __syncthreads();

        if (tid < 60) {
            int b = tid / 30, i = tid - b * 30;
            const float* rp = red + (b * 30 + i) * 4;
            xls[b * 30 + i] = fmaxf(rp[0] + rp[1] + rp[2] + rp[3] + __ldg(bling), 0.f);
        }
        __syncthreads();
        if (tid < 18) {
            int b = tid / 9, c = tid - b * 9;
            float s = __ldg(bheadg + c);
            #pragma unroll
            for (int i = 0; i < 30; ++i)
                s = fmaf(xls[b * 30 + i], __ldg(Wheadg + c * 30 + i), s);
            out[(size_t)(tile * 2 + b) * 9 + c] = s;
        }
        // next iteration's wait+sync orders stage/red/xl reuse
    }
}

// =====================================================================
extern "C" void kernel_launch(void* const* d_in, const int* in_sizes, int n_in,
                              void* d_out, int out_size) {
    const float* real  = (const float*)d_in[0];
    const float* graph = (const float*)d_in[2];
    const float* W1    = (const float*)d_in[3];
    const float* b1    = (const float*)d_in[4];
    const float* W2    = (const float*)d_in[5];
    const float* b2    = (const float*)d_in[6];
    const float* wlin  = (const float*)d_in[7];
    const float* blin  = (const float*)d_in[8];
    const float* Whead = (const float*)d_in[9];
    const float* bhead = (const float*)d_in[10];
    float* out = (float*)d_out;

    float *adj_p;
    __half *y1_p, *h1_p, *w1_p, *w2_p;
    cudaGetSymbolAddress((void**)&adj_p, g_adj);
    cudaGetSymbolAddress((void**)&y1_p,  g_y1);
    cudaGetSymbolAddress((void**)&h1_p,  g_h1);
    cudaGetSymbolAddress((void**)&w1_p,  g_w1);
    cudaGetSymbolAddress((void**)&w2_p,  g_w2);

    cudaFuncSetAttribute(gemm_persist, cudaFuncAttributeMaxDynamicSharedMemorySize, PSM_TOTAL);
    cudaFuncSetAttribute(gemm_fused,   cudaFuncAttributeMaxDynamicSharedMemorySize, GF_TOTAL);

    // 1. weight transpose to fp16 [N,K]
    prep_w<<<256, 256>>>(W1, W2, w1_p, w2_p);
    // 2. adj = mean(graph); y1 = adj @ real (fp16)
    k_prep<<<BATCH, 128>>>(graph, real, adj_p, y1_p);
    // 3. h1 = relu(y1 @ W1 + b1)  (persistent, W1 resident)
    gemm_persist<<<PGRID, 512, PSM_TOTAL>>>(y1_p, w1_p, b1, h1_p);
    // 4. fused: u2 = h1 @ W2 (smem) ; g2 = adj@u2 ; wlin/blin/head -> out
    gemm_fused<<<PGRID, 512, GF_TOTAL>>>(h1_p, w2_p, adj_p, b2, wlin, blin,
                                         Whead, bhead, out);
}